// round 4
// baseline (speedup 1.0000x reference)
#include <cuda_runtime.h>

#define T_STEPS 2048
#define B_SIZE  4096
#define OUTD    4
#define BLOCK_THREADS 256

typedef unsigned long long u64;

// ---------- packed f32x2 helpers (sm_100a) ----------
__device__ __forceinline__ u64 pack2(float lo, float hi) {
    u64 r;
    asm("mov.b64 %0, {%1, %2};"
        : "=l"(r) : "r"(__float_as_uint(lo)), "r"(__float_as_uint(hi)));
    return r;
}
__device__ __forceinline__ float hadd2(u64 v) {
    unsigned a, b;
    asm("mov.b64 {%0, %1}, %2;" : "=r"(a), "=r"(b) : "l"(v));
    return __uint_as_float(a) + __uint_as_float(b);
}
__device__ __forceinline__ u64 fma2(u64 a, u64 b, u64 c) {
    u64 d;
    asm("fma.rn.f32x2 %0, %1, %2, %3;" : "=l"(d) : "l"(a), "l"(b), "l"(c));
    return d;
}
__device__ __forceinline__ u64 add2(u64 a, u64 b) {
    u64 d;
    asm("add.rn.f32x2 %0, %1, %2;" : "=l"(d) : "l"(a), "l"(b));
    return d;
}

// ---------- fast activations (accurate: ex2 + rcp.approx, ~1e-7) ----------
__device__ __forceinline__ float ex2f(float x) {
    float r; asm("ex2.approx.f32 %0, %1;" : "=f"(r) : "f"(x)); return r;
}
__device__ __forceinline__ float rcpf(float x) {
    float r; asm("rcp.approx.f32 %0, %1;" : "=f"(r) : "f"(x)); return r;
}
__device__ __forceinline__ float sigmoid_fast(float x) {
    // 1/(1+e^-x); saturates correctly at +/-inf
    return rcpf(1.0f + ex2f(-1.442695041f * x));
}
__device__ __forceinline__ float tanh_fast(float x) {
    // tanh(x) = 1 - 2/(e^{2x}+1); overflow-safe both directions
    float e = ex2f(2.885390082f * x);
    return fmaf(-2.0f, rcpf(e + 1.0f), 1.0f);
}

// broadcast 8-group value s into 4 packed pairs (k-pairs 01,23,45,67)
__device__ __forceinline__ void bc_pack(float s, u64 (&p)[4]) {
    float v0 = __shfl_sync(0xffffffffu, s, 0, 8);
    float v1 = __shfl_sync(0xffffffffu, s, 1, 8);
    float v2 = __shfl_sync(0xffffffffu, s, 2, 8);
    float v3 = __shfl_sync(0xffffffffu, s, 3, 8);
    float v4 = __shfl_sync(0xffffffffu, s, 4, 8);
    float v5 = __shfl_sync(0xffffffffu, s, 5, 8);
    float v6 = __shfl_sync(0xffffffffu, s, 6, 8);
    float v7 = __shfl_sync(0xffffffffu, s, 7, 8);
    p[0] = pack2(v0, v1);
    p[1] = pack2(v2, v3);
    p[2] = pack2(v4, v5);
    p[3] = pack2(v6, v7);
}

// packed dot over 8 (4 pairs), seeded
__device__ __forceinline__ u64 dot4(const u64 (&w)[4], const u64 (&p)[4], u64 seed) {
    u64 a = fma2(w[0], p[0], seed);
    a = fma2(w[1], p[1], a);
    a = fma2(w[2], p[2], a);
    a = fma2(w[3], p[3], a);
    return a;
}

__global__ void __launch_bounds__(BLOCK_THREADS, 1)
gru3_fused_kernel(const float* __restrict__ x,
                  const float* __restrict__ Wih0, const float* __restrict__ Whh0,
                  const float* __restrict__ bih0, const float* __restrict__ bhh0,
                  const float* __restrict__ Wih1, const float* __restrict__ Whh1,
                  const float* __restrict__ bih1, const float* __restrict__ bhh1,
                  const float* __restrict__ Wih2, const float* __restrict__ Whh2,
                  const float* __restrict__ bih2, const float* __restrict__ bhh2,
                  const float* __restrict__ fcW,  const float* __restrict__ fcb,
                  float* __restrict__ out)
{
    const int g   = blockIdx.x * BLOCK_THREADS + threadIdx.x;
    const int b   = g >> 3;       // batch element
    const int sub = g & 7;        // hidden unit owned by this lane

    // ---- packed register-resident weights ----
    u64 whh0[3][4], whh1[3][4], whh2[3][4];
    u64 wih1[3][4], wih2[3][4];
    u64 wx0[3];

    const float2* Whh0v = (const float2*)Whh0;
    const float2* Whh1v = (const float2*)Whh1;
    const float2* Whh2v = (const float2*)Whh2;
    const float2* Wih1v = (const float2*)Wih1;
    const float2* Wih2v = (const float2*)Wih2;
    const float2* Wih0v = (const float2*)Wih0;

#pragma unroll
    for (int gt = 0; gt < 3; gt++) {
        const int row = gt * 8 + sub;
#pragma unroll
        for (int kk = 0; kk < 4; kk++) {
            float2 a = Whh0v[row * 4 + kk]; whh0[gt][kk] = pack2(a.x, a.y);
            float2 c = Whh1v[row * 4 + kk]; whh1[gt][kk] = pack2(c.x, c.y);
            float2 e = Whh2v[row * 4 + kk]; whh2[gt][kk] = pack2(e.x, e.y);
            float2 d = Wih1v[row * 4 + kk]; wih1[gt][kk] = pack2(d.x, d.y);
            float2 f = Wih2v[row * 4 + kk]; wih2[gt][kk] = pack2(f.x, f.y);
        }
        float2 w0 = Wih0v[row];  // F=2
        wx0[gt] = pack2(w0.x, w0.y);
    }

    // bias seeds (packed into lane0 of the chain seed)
    const u64 sR0  = pack2(bih0[sub]     + bhh0[sub],     0.0f);
    const u64 sZ0  = pack2(bih0[8 + sub] + bhh0[8 + sub], 0.0f);
    const u64 sNx0 = pack2(bih0[16 + sub], 0.0f);
    const u64 sNh0 = pack2(bhh0[16 + sub], 0.0f);
    const u64 sR1  = pack2(bih1[sub]     + bhh1[sub],     0.0f);
    const u64 sZ1  = pack2(bih1[8 + sub] + bhh1[8 + sub], 0.0f);
    const u64 sNx1 = pack2(bih1[16 + sub], 0.0f);
    const u64 sNh1 = pack2(bhh1[16 + sub], 0.0f);
    const u64 sR2  = pack2(bih2[sub]     + bhh2[sub],     0.0f);
    const u64 sZ2  = pack2(bih2[8 + sub] + bhh2[8 + sub], 0.0f);
    const u64 sNx2 = pack2(bih2[16 + sub], 0.0f);
    const u64 sNh2 = pack2(bhh2[16 + sub], 0.0f);

    // ---- recurrence state ----
    float h0 = 0.0f, h1 = 0.0f, h2 = 0.0f, acc = 0.0f;

    const float* xp = x + (size_t)b * 2;
    float x0 = __ldg(xp);
    float x1 = __ldg(xp + 1);
    xp += B_SIZE * 2;

    auto step = [&](float cx0, float cx1) {
        // --- early, independent: broadcast h(t-1) for all layers + hh partials ---
        u64 p0[4], p1[4], p2[4];
        bc_pack(h0, p0);
        bc_pack(h1, p1);
        bc_pack(h2, p2);

        const u64 px = pack2(cx0, cx1);
        u64 a0R  = dot4(whh0[0], p0, fma2(wx0[0], px, sR0));
        u64 a0Z  = dot4(whh0[1], p0, fma2(wx0[1], px, sZ0));
        u64 a0Nh = dot4(whh0[2], p0, sNh0);
        float nx0g = hadd2(fma2(wx0[2], px, sNx0));

        u64 a1Rh = dot4(whh1[0], p1, sR1);
        u64 a1Zh = dot4(whh1[1], p1, sZ1);
        u64 a1Nh = dot4(whh1[2], p1, sNh1);
        u64 a2Rh = dot4(whh2[0], p2, sR2);
        u64 a2Zh = dot4(whh2[1], p2, sZ2);
        u64 a2Nh = dot4(whh2[2], p2, sNh2);

        // --- layer 0 finish ---
        float r0 = sigmoid_fast(hadd2(a0R));
        float z0 = sigmoid_fast(hadd2(a0Z));
        float n0 = tanh_fast(fmaf(r0, hadd2(a0Nh), nx0g));
        h0 = fmaf(z0, h0 - n0, n0);

        // --- layer 1: vin = h0(t) ---
        u64 q0[4];
        bc_pack(h0, q0);
        float r1  = sigmoid_fast(hadd2(add2(dot4(wih1[0], q0, 0ULL), a1Rh)));
        float z1  = sigmoid_fast(hadd2(add2(dot4(wih1[1], q0, 0ULL), a1Zh)));
        float n1x = hadd2(dot4(wih1[2], q0, sNx1));
        float n1  = tanh_fast(fmaf(r1, hadd2(a1Nh), n1x));
        h1 = fmaf(z1, h1 - n1, n1);

        // --- layer 2: vin = h1(t) ---
        u64 q1[4];
        bc_pack(h1, q1);
        float r2  = sigmoid_fast(hadd2(add2(dot4(wih2[0], q1, 0ULL), a2Rh)));
        float z2  = sigmoid_fast(hadd2(add2(dot4(wih2[1], q1, 0ULL), a2Zh)));
        float n2x = hadd2(dot4(wih2[2], q1, sNx2));
        float n2  = tanh_fast(fmaf(r2, hadd2(a2Nh), n2x));
        h2 = fmaf(z2, h2 - n2, n2);

        acc += h2;
    };

#pragma unroll 2
    for (int t = 0; t < T_STEPS - 1; t++) {
        float nx0 = __ldg(xp);
        float nx1 = __ldg(xp + 1);
        xp += B_SIZE * 2;
        step(x0, x1);
        x0 = nx0;
        x1 = nx1;
    }
    step(x0, x1);  // last step, no prefetch

    // ---- mean over T, then FC (OUT=4) ----
    const float mean = acc * (1.0f / (float)T_STEPS);
    float m[8];
#pragma unroll
    for (int k = 0; k < 8; k++)
        m[k] = __shfl_sync(0xffffffffu, mean, k, 8);

    if (sub < OUTD) {
        float o = __ldg(fcb + sub);
#pragma unroll
        for (int k = 0; k < 8; k++)
            o = fmaf(__ldg(fcW + sub * 8 + k), m[k], o);
        out[(size_t)b * OUTD + sub] = o;
    }
}

extern "C" void kernel_launch(void* const* d_in, const int* in_sizes, int n_in,
                              void* d_out, int out_size)
{
    const float* x    = (const float*)d_in[0];
    const float* Wih0 = (const float*)d_in[1];
    const float* Whh0 = (const float*)d_in[2];
    const float* bih0 = (const float*)d_in[3];
    const float* bhh0 = (const float*)d_in[4];
    const float* Wih1 = (const float*)d_in[5];
    const float* Whh1 = (const float*)d_in[6];
    const float* bih1 = (const float*)d_in[7];
    const float* bhh1 = (const float*)d_in[8];
    const float* Wih2 = (const float*)d_in[9];
    const float* Whh2 = (const float*)d_in[10];
    const float* bih2 = (const float*)d_in[11];
    const float* bhh2 = (const float*)d_in[12];
    const float* fcW  = (const float*)d_in[13];
    const float* fcb  = (const float*)d_in[14];
    float* out = (float*)d_out;

    const int total_threads = B_SIZE * 8;              // 32768
    const int blocks = total_threads / BLOCK_THREADS;  // 128

    gru3_fused_kernel<<<blocks, BLOCK_THREADS>>>(
        x,
        Wih0, Whh0, bih0, bhh0,
        Wih1, Whh1, bih1, bhh1,
        Wih2, Whh2, bih2, bhh2,
        fcW, fcb, out);
}

// round 5
// speedup vs baseline: 1.4035x; 1.4035x over previous
#include <cuda_runtime.h>

#define T_STEPS 2048
#define B_SIZE  4096
#define OUTD    4
#define BLOCK_THREADS 64

typedef unsigned long long u64;

// ---------- packed f32x2 helpers (sm_100a) ----------
__device__ __forceinline__ u64 pack2(float lo, float hi) {
    u64 r;
    asm("mov.b64 %0, {%1, %2};"
        : "=l"(r) : "r"(__float_as_uint(lo)), "r"(__float_as_uint(hi)));
    return r;
}
__device__ __forceinline__ float hadd2(u64 v) {
    unsigned a, b;
    asm("mov.b64 {%0, %1}, %2;" : "=r"(a), "=r"(b) : "l"(v));
    return __uint_as_float(a) + __uint_as_float(b);
}
__device__ __forceinline__ u64 fma2(u64 a, u64 b, u64 c) {
    u64 d;
    asm("fma.rn.f32x2 %0, %1, %2, %3;" : "=l"(d) : "l"(a), "l"(b), "l"(c));
    return d;
}
__device__ __forceinline__ u64 add2(u64 a, u64 b) {
    u64 d;
    asm("add.rn.f32x2 %0, %1, %2;" : "=l"(d) : "l"(a), "l"(b));
    return d;
}

// ---------- MUFU activations (short latency) ----------
__device__ __forceinline__ float tanh_mufu(float x) {
    float r; asm("tanh.approx.f32 %0, %1;" : "=f"(r) : "f"(x)); return r;
}
__device__ __forceinline__ float sigmoid_mufu(float x) {
    // sigmoid(x) = 0.5*tanh(0.5x) + 0.5
    return fmaf(0.5f, tanh_mufu(0.5f * x), 0.5f);
}

// broadcast 8-group value s into 4 packed pairs (k-pairs 01,23,45,67)
__device__ __forceinline__ void bc_pack(float s, u64 (&p)[4]) {
    float v0 = __shfl_sync(0xffffffffu, s, 0, 8);
    float v1 = __shfl_sync(0xffffffffu, s, 1, 8);
    float v2 = __shfl_sync(0xffffffffu, s, 2, 8);
    float v3 = __shfl_sync(0xffffffffu, s, 3, 8);
    float v4 = __shfl_sync(0xffffffffu, s, 4, 8);
    float v5 = __shfl_sync(0xffffffffu, s, 5, 8);
    float v6 = __shfl_sync(0xffffffffu, s, 6, 8);
    float v7 = __shfl_sync(0xffffffffu, s, 7, 8);
    p[0] = pack2(v0, v1);
    p[1] = pack2(v2, v3);
    p[2] = pack2(v4, v5);
    p[3] = pack2(v6, v7);
}

// tree-shaped packed dot over 8 (4 pairs), seeded; returns horizontal sum
__device__ __forceinline__ float dot8(const u64 (&w)[4], const u64 (&p)[4], u64 seed) {
    u64 a = fma2(w[0], p[0], seed);
    u64 b = fma2(w[1], p[1], 0ULL);
    a = fma2(w[2], p[2], a);
    b = fma2(w[3], p[3], b);
    return hadd2(add2(a, b));
}

__global__ void __launch_bounds__(BLOCK_THREADS, 1)
gru3_fused_kernel(const float* __restrict__ x,
                  const float* __restrict__ Wih0, const float* __restrict__ Whh0,
                  const float* __restrict__ bih0, const float* __restrict__ bhh0,
                  const float* __restrict__ Wih1, const float* __restrict__ Whh1,
                  const float* __restrict__ bih1, const float* __restrict__ bhh1,
                  const float* __restrict__ Wih2, const float* __restrict__ Whh2,
                  const float* __restrict__ bih2, const float* __restrict__ bhh2,
                  const float* __restrict__ fcW,  const float* __restrict__ fcb,
                  float* __restrict__ out)
{
    const int g   = blockIdx.x * BLOCK_THREADS + threadIdx.x;
    const int b   = g >> 3;       // batch element
    const int sub = g & 7;        // hidden unit owned by this lane

    // ---- packed register-resident weights ----
    u64 whh0[3][4], whh1[3][4], whh2[3][4];
    u64 wih1[3][4], wih2[3][4];
    u64 wx0[3];

    const float2* Whh0v = (const float2*)Whh0;
    const float2* Whh1v = (const float2*)Whh1;
    const float2* Whh2v = (const float2*)Whh2;
    const float2* Wih1v = (const float2*)Wih1;
    const float2* Wih2v = (const float2*)Wih2;
    const float2* Wih0v = (const float2*)Wih0;

#pragma unroll
    for (int gt = 0; gt < 3; gt++) {
        const int row = gt * 8 + sub;
#pragma unroll
        for (int kk = 0; kk < 4; kk++) {
            float2 a = Whh0v[row * 4 + kk]; whh0[gt][kk] = pack2(a.x, a.y);
            float2 c = Whh1v[row * 4 + kk]; whh1[gt][kk] = pack2(c.x, c.y);
            float2 e = Whh2v[row * 4 + kk]; whh2[gt][kk] = pack2(e.x, e.y);
            float2 d = Wih1v[row * 4 + kk]; wih1[gt][kk] = pack2(d.x, d.y);
            float2 f = Wih2v[row * 4 + kk]; wih2[gt][kk] = pack2(f.x, f.y);
        }
        float2 w0 = Wih0v[row];  // F=2
        wx0[gt] = pack2(w0.x, w0.y);
    }

    // bias seeds (bias lives in lane0 of the packed seed)
    const u64 sR0  = pack2(bih0[sub]     + bhh0[sub],     0.0f);
    const u64 sZ0  = pack2(bih0[8 + sub] + bhh0[8 + sub], 0.0f);
    const u64 sNx0 = pack2(bih0[16 + sub], 0.0f);
    const u64 sNh0 = pack2(bhh0[16 + sub], 0.0f);
    const u64 sR1  = pack2(bih1[sub]     + bhh1[sub],     0.0f);
    const u64 sZ1  = pack2(bih1[8 + sub] + bhh1[8 + sub], 0.0f);
    const u64 sNx1 = pack2(bih1[16 + sub], 0.0f);
    const u64 sNh1 = pack2(bhh1[16 + sub], 0.0f);
    const u64 sR2  = pack2(bih2[sub]     + bhh2[sub],     0.0f);
    const u64 sZ2  = pack2(bih2[8 + sub] + bhh2[8 + sub], 0.0f);
    const u64 sNx2 = pack2(bih2[16 + sub], 0.0f);
    const u64 sNh2 = pack2(bhh2[16 + sub], 0.0f);

    // ---- recurrence state: scalars + persistent packed broadcasts ----
    float h0 = 0.0f, h1 = 0.0f, h2 = 0.0f, acc = 0.0f;
    u64 P0[4], P1[4], P2[4];   // broadcast of h(t-1) per layer, carried across steps
#pragma unroll
    for (int k = 0; k < 4; k++) { P0[k] = 0ULL; P1[k] = 0ULL; P2[k] = 0ULL; }

    const float* xp = x + (size_t)b * 2;
    float x0 = __ldg(xp);
    float x1 = __ldg(xp + 1);
    xp += B_SIZE * 2;

    auto step = [&](float cx0, float cx1) {
        // ---- hh partials for all layers use P* (h at t-1): fully independent ----
        const u64 px = pack2(cx0, cx1);
        float a0R  = dot8(whh0[0], P0, fma2(wx0[0], px, sR0));
        float a0Nh = dot8(whh0[2], P0, sNh0);
        float a0Z  = dot8(whh0[1], P0, fma2(wx0[1], px, sZ0));
        float nx0g = hadd2(fma2(wx0[2], px, sNx0));

        float a1Rh = dot8(whh1[0], P1, sR1);
        float a1Nh = dot8(whh1[2], P1, sNh1);
        float a1Zh = dot8(whh1[1], P1, sZ1);
        float a2Rh = dot8(whh2[0], P2, sR2);
        float a2Nh = dot8(whh2[2], P2, sNh2);
        float a2Zh = dot8(whh2[1], P2, sZ2);

        // ---- layer 0 finish (r first: it gates n on the critical path) ----
        float r0 = sigmoid_mufu(a0R);
        float z0 = sigmoid_mufu(a0Z);
        float n0 = tanh_mufu(fmaf(r0, a0Nh, nx0g));
        h0 = fmaf(z0, h0 - n0, n0);
        bc_pack(h0, P0);                 // single broadcast, reused next step

        // ---- layer 1: vin = h0(t) via P0 ----
        float r1 = sigmoid_mufu(dot8(wih1[0], P0, 0ULL) + a1Rh);
        float z1 = sigmoid_mufu(dot8(wih1[1], P0, 0ULL) + a1Zh);
        float n1 = tanh_mufu(fmaf(r1, a1Nh, dot8(wih1[2], P0, sNx1)));
        h1 = fmaf(z1, h1 - n1, n1);
        bc_pack(h1, P1);

        // ---- layer 2: vin = h1(t) via P1 ----
        float r2 = sigmoid_mufu(dot8(wih2[0], P1, 0ULL) + a2Rh);
        float z2 = sigmoid_mufu(dot8(wih2[1], P1, 0ULL) + a2Zh);
        float n2 = tanh_mufu(fmaf(r2, a2Nh, dot8(wih2[2], P1, sNx2)));
        h2 = fmaf(z2, h2 - n2, n2);
        bc_pack(h2, P2);

        acc += h2;
    };

#pragma unroll 2
    for (int t = 0; t < T_STEPS - 1; t++) {
        float nx0 = __ldg(xp);
        float nx1 = __ldg(xp + 1);
        xp += B_SIZE * 2;
        step(x0, x1);
        x0 = nx0;
        x1 = nx1;
    }
    step(x0, x1);  // last step, no prefetch

    // ---- mean over T, then FC (OUT=4) ----
    const float mean = acc * (1.0f / (float)T_STEPS);
    float m[8];
#pragma unroll
    for (int k = 0; k < 8; k++)
        m[k] = __shfl_sync(0xffffffffu, mean, k, 8);

    if (sub < OUTD) {
        float o = __ldg(fcb + sub);
#pragma unroll
        for (int k = 0; k < 8; k++)
            o = fmaf(__ldg(fcW + sub * 8 + k), m[k], o);
        out[(size_t)b * OUTD + sub] = o;
    }
}

extern "C" void kernel_launch(void* const* d_in, const int* in_sizes, int n_in,
                              void* d_out, int out_size)
{
    const float* x    = (const float*)d_in[0];
    const float* Wih0 = (const float*)d_in[1];
    const float* Whh0 = (const float*)d_in[2];
    const float* bih0 = (const float*)d_in[3];
    const float* bhh0 = (const float*)d_in[4];
    const float* Wih1 = (const float*)d_in[5];
    const float* Whh1 = (const float*)d_in[6];
    const float* bih1 = (const float*)d_in[7];
    const float* bhh1 = (const float*)d_in[8];
    const float* Wih2 = (const float*)d_in[9];
    const float* Whh2 = (const float*)d_in[10];
    const float* bih2 = (const float*)d_in[11];
    const float* bhh2 = (const float*)d_in[12];
    const float* fcW  = (const float*)d_in[13];
    const float* fcb  = (const float*)d_in[14];
    float* out = (float*)d_out;

    const int total_threads = B_SIZE * 8;              // 32768
    const int blocks = total_threads / BLOCK_THREADS;  // 512 -> fills all 148 SMs

    gru3_fused_kernel<<<blocks, BLOCK_THREADS>>>(
        x,
        Wih0, Whh0, bih0, bhh0,
        Wih1, Whh1, bih1, bhh1,
        Wih2, Whh2, bih2, bhh2,
        fcW, fcb, out);
}